// round 13
// baseline (speedup 1.0000x reference)
#include <cuda_runtime.h>
#include <cstdint>

// MarginalCalibrationPlot: per-(class, bin) calibration stats.
// probas: [N, C] float32 row-major, labels: [N] int32 or int64.
// Output: [confs(C*B) | accs(C*B) | n_samples(C*B)] float32, seg = c*B + b.

#define CCOUNT 100
#define NBINS  15
#define NSEG   (CCOUNT * NBINS)
#define TPB    512
#define ACTIVE 500          // active threads; multiple of CCOUNT
#define GRID_ACC 304        // 2 blocks/SM on 152-SM GB300
#define INV15  (1.0f / 15.0f)

// Per-block partials: [cnt(1500) | sum_p(1500) | sum_acc(1500)] per block.
// Fully rewritten every run => no zero-init kernel needed.
__device__ float g_part[GRID_ACC][3 * NSEG];

// Exact replication of jnp.linspace(0,1,16,f32) binning:
// edge[k] = fl(k * fl(1/15)); fl(15*fl(1/15)) == 1.0f exactly, so the
// endpoint override is automatic. floor(p*15) is within +-1 of the
// searchsorted(side='right')-1 bin; two one-sided corrections fix it.
// valid = p > max(edge[k], 0.01): for k>=1 edge>=0.0667>0.01, for k==0
// edge=0 -> reduces to p>0.01; exactly matches the reference predicate.
#define BINOF(P, KF, W) do {                                              \
    KF = floorf((P) * 15.0f);                                             \
    float eh_ = fmaf(KF, INV15, INV15);                                   \
    KF += (eh_ <= (P)) ? 1.0f : 0.0f;                                     \
    float el_ = KF * INV15;                                               \
    KF -= (el_ > (P)) ? 1.0f : 0.0f;                                      \
    float lf_ = KF * INV15;                                               \
    W = ((P) > fmaxf(lf_, 0.01f)) ? 1.0f : 0.0f;                          \
} while (0)

__global__ void __launch_bounds__(TPB, 2) accum_kernel(
    const float* __restrict__ probas,
    const void*  __restrict__ labels,
    int N)
{
    // [NBINS][TPB] float2 {count, sum_p}: per-thread-private slots,
    // zero atomics / zero branches in the 50M-element loop.
    extern __shared__ float2 s2[];
    __shared__ float s_acc[NSEG];
    __shared__ int   s_ok;

    const int t = threadIdx.x;
    #pragma unroll
    for (int b = 0; b < NBINS; ++b) s2[b * TPB + t] = make_float2(0.0f, 0.0f);
    for (int i = t; i < NSEG; i += TPB) s_acc[i] = 0.0f;
    if (t == 0) s_ok = 1;
    __syncthreads();

    // labels dtype detect: int32 read as int64 pairs two labels; any
    // nonzero hi word makes v >= 2^32. P(128 hi==0 | int32) ~ 1e-256.
    {
        int nchk = (N >= 256) ? 128 : (N / 2);
        if (t < nchk) {
            long long v = ((const long long*)labels)[t];
            if (v < 0 || v >= CCOUNT) atomicAnd(&s_ok, 0);
        }
    }
    __syncthreads();
    const int sh = s_ok;                                // 1 if int64
    const int* __restrict__ l32 = (const int*)labels;   // low word = label

    const long long E     = (long long)N * CCOUNT;
    const long long units = E / ACTIVE;                 // 500-elem groups
    const int       rem   = (int)(E - units * ACTIVE);  // multiple of 100
    const long long perBlk = (units + gridDim.x - 1) / gridDim.x;
    const long long u0 = (long long)blockIdx.x * perBlk;
    long long u1 = u0 + perBlk; if (u1 > units) u1 = units;

    // ---- accuracy pass: only column labels[r] of row r can contribute.
    // 500k gathers total (~1.6k rows/block) instead of 50M label checks.
    {
        const long long r1 = u1 * 5;
        for (long long r = u0 * 5 + t; r < r1; r += TPB) {
            int lb = l32[r << sh];
            float p = probas[r * CCOUNT + lb];
            float kf, w; BINOF(p, kf, w);
            if (w != 0.0f) {
                int bi = (int)fminf(kf, 14.0f);
                atomicAdd(&s_acc[lb * NBINS + bi], 1.0f);
            }
        }
        if (blockIdx.x == 0) {          // tail rows (N rows not mult of 5)
            for (long long r = units * 5 + t; r < N; r += TPB) {
                int lb = l32[r << sh];
                float p = probas[r * CCOUNT + lb];
                float kf, w; BINOF(p, kf, w);
                if (w != 0.0f) {
                    int bi = (int)fminf(kf, 14.0f);
                    atomicAdd(&s_acc[lb * NBINS + bi], 1.0f);
                }
            }
        }
    }

    // ---- main loop: count + sum_p only, branchless, fixed column t%100.
    #define BODY(P) do {                                                  \
        float p_ = (P);                                                   \
        float kf_, w_; BINOF(p_, kf_, w_);                                \
        int bi_ = (int)fminf(kf_, 14.0f);                                 \
        float2* sp_ = &s2[bi_ * TPB + t];                                 \
        float2 v_ = *sp_;                                                 \
        v_.x += w_;                                                       \
        v_.y = fmaf(w_, p_, v_.y);                                        \
        *sp_ = v_;                                                        \
    } while (0)

    if (t < ACTIVE && u0 < u1) {
        const float* pp = probas + u0 * ACTIVE + t;
        const long long nu = u1 - u0;
        long long i = 0;
        for (; i + 8 <= nu; i += 8) {
            float p[8];
            #pragma unroll
            for (int j = 0; j < 8; ++j) p[j] = pp[j * ACTIVE];
            #pragma unroll
            for (int j = 0; j < 8; ++j) BODY(p[j]);
            pp += 8 * ACTIVE;
        }
        for (; i < nu; ++i) { BODY(pp[0]); pp += ACTIVE; }
    }
    // element tail (rem multiple of 100 => column map stays consistent)
    if (blockIdx.x == 0 && t < rem) BODY(probas[units * ACTIVE + t]);
    #undef BODY
    __syncthreads();

    // ---- epilogue: fold 5 sub-slots per (col,bin); coalesced stores.
    float* gp = g_part[blockIdx.x];
    for (int idx = t; idx < NSEG; idx += TPB) {       // idx = col*NBINS+b
        const int b   = idx % NBINS;
        const int col = idx / NBINS;
        float cx = 0.0f, sy = 0.0f;
        #pragma unroll
        for (int j = 0; j < 5; ++j) {
            float2 v = s2[b * TPB + col + j * CCOUNT];
            cx += v.x; sy += v.y;
        }
        gp[idx]            = cx;
        gp[NSEG + idx]     = sy;
        gp[2 * NSEG + idx] = s_acc[idx];
    }
}

// -------- finalize: reduce 304 L2-resident partials, apply NaN rule --------
__global__ void finalize_kernel(float* __restrict__ out) {
    int k = blockIdx.x * blockDim.x + threadIdx.x;
    if (k >= NSEG) return;
    float cnt = 0.0f, sum = 0.0f, acc = 0.0f;
    #pragma unroll 8
    for (int b = 0; b < GRID_ACC; ++b) {
        const float* gp = g_part[b];
        cnt += gp[k];
        sum += gp[NSEG + k];
        acc += gp[2 * NSEG + k];
    }
    float conf, a;
    if (cnt > 0.0f) {
        conf = sum / cnt;
        a    = acc / cnt;
    } else {
        conf = __int_as_float(0x7fc00000);
        a    = conf;
    }
    out[k]            = conf;
    out[NSEG + k]     = a;
    out[2 * NSEG + k] = cnt;
}

extern "C" void kernel_launch(void* const* d_in, const int* in_sizes, int n_in,
                              void* d_out, int out_size) {
    const float* probas = (const float*)d_in[0];
    const void*  labels = d_in[1];
    const int N = in_sizes[0] / CCOUNT;

    const size_t smem = (size_t)NBINS * TPB * sizeof(float2);  // 61440 B
    cudaFuncSetAttribute(accum_kernel,
                         cudaFuncAttributeMaxDynamicSharedMemorySize, (int)smem);

    accum_kernel<<<GRID_ACC, TPB, smem>>>(probas, labels, N);
    finalize_kernel<<<(NSEG + 127) / 128, 128>>>((float*)d_out);
}

// round 14
// speedup vs baseline: 1.2916x; 1.2916x over previous
#include <cuda_runtime.h>
#include <cstdint>

// MarginalCalibrationPlot: per-(class, bin) calibration stats.
// probas: [N, C] float32 row-major, labels: [N] int32 or int64.
// Output: [confs(C*B) | accs(C*B) | n_samples(C*B)] float32, seg = c*B + b.

#define CCOUNT 100
#define NBINS  15
#define NSEG   (CCOUNT * NBINS)
#define TPB    512
#define ACTIVE 500          // active threads; multiple of CCOUNT
#define GRID_ACC 304        // 2 blocks/SM on 152-SM GB300
#define SROWS  16           // 15 real bins + 1 overflow row (kf==15 <=> w==0)
#define INV15  (1.0f / 15.0f)
#define FBLK   256

// Per-block partials: [cnt(1500) | sum_p(1500) | sum_acc(1500)] per block.
// Fully rewritten every run => no zero-init kernel needed.
__device__ float g_part[GRID_ACC][3 * NSEG];

// Exact replication of jnp.linspace(0,1,16,f32) + searchsorted(side='right')-1:
// edge[k] = fl(k * fl(1/15)); fl(15*fl(1/15)) == 1.0f exactly.
// Proof sketch: p >= edge[k] => fl(p*15) >= k (fl monotone; fl(edge[k]*15)
// rounds to exactly k since its offset from k is < half-ulp), so
// floor(fl(p*15)) >= true_bin always — only ONE downward correction needed.
// valid = p > max(edge[k], 0.01): edge[k>=1] > 0.01, edge[0]=0 -> p>0.01.
#define BINOF(P, KF, W) do {                                              \
    KF = floorf((P) * 15.0f);                                             \
    float el_ = KF * INV15;                                               \
    KF -= (el_ > (P)) ? 1.0f : 0.0f;                                      \
    float lf_ = KF * INV15;                                               \
    W = ((P) > fmaxf(lf_, 0.01f)) ? 1.0f : 0.0f;                          \
} while (0)

__global__ void __launch_bounds__(TPB, 2) accum_kernel(
    const float* __restrict__ probas,
    const void*  __restrict__ labels,
    int N)
{
    // [SROWS][TPB] float2 {count, sum_p}: per-thread-private slots,
    // zero atomics / zero branches in the 50M-element loop.
    extern __shared__ float2 s2[];
    __shared__ float s_acc[NSEG];
    __shared__ int   s_ok;

    const int t = threadIdx.x;
    #pragma unroll
    for (int b = 0; b < SROWS; ++b) s2[b * TPB + t] = make_float2(0.0f, 0.0f);
    for (int i = t; i < NSEG; i += TPB) s_acc[i] = 0.0f;
    if (t == 0) s_ok = 1;
    __syncthreads();

    // labels dtype detect: int32 read as int64 pairs two labels; any
    // nonzero hi word makes v >= 2^32. P(128 hi==0 | int32) ~ 1e-256.
    {
        int nchk = (N >= 256) ? 128 : (N / 2);
        if (t < nchk) {
            long long v = ((const long long*)labels)[t];
            if (v < 0 || v >= CCOUNT) atomicAnd(&s_ok, 0);
        }
    }
    __syncthreads();
    const int sh = s_ok;                                // 1 if int64
    const int* __restrict__ l32 = (const int*)labels;   // low word = label

    const long long E     = (long long)N * CCOUNT;
    const long long units = E / ACTIVE;                 // 500-elem groups
    const int       rem   = (int)(E - units * ACTIVE);  // multiple of 100
    const long long perBlk = (units + gridDim.x - 1) / gridDim.x;
    const long long u0 = (long long)blockIdx.x * perBlk;
    long long u1 = u0 + perBlk; if (u1 > units) u1 = units;

    // ---- accuracy pass: only column labels[r] of row r can contribute.
    // 500k gathers total instead of 50M label checks in the hot loop.
    // Inside w!=0, kf<=14 is guaranteed (kf==15 => left edge 1.0 => w==0).
    {
        const long long r1 = u1 * 5;
        for (long long r = u0 * 5 + t; r < r1; r += TPB) {
            int lb = l32[r << sh];
            float p = probas[r * CCOUNT + lb];
            float kf, w; BINOF(p, kf, w);
            if (w != 0.0f) atomicAdd(&s_acc[lb * NBINS + (int)kf], 1.0f);
        }
        if (blockIdx.x == 0) {          // tail rows (N not mult of 5)
            for (long long r = units * 5 + t; r < N; r += TPB) {
                int lb = l32[r << sh];
                float p = probas[r * CCOUNT + lb];
                float kf, w; BINOF(p, kf, w);
                if (w != 0.0f) atomicAdd(&s_acc[lb * NBINS + (int)kf], 1.0f);
            }
        }
    }

    // ---- main loop: count + sum_p only, branchless, fixed column t%100.
    // kf==15 routes to overflow row 15 with w==0 (writes value back unchanged).
    #define BODY(P) do {                                                  \
        float p_ = (P);                                                   \
        float kf_, w_; BINOF(p_, kf_, w_);                                \
        float2* sp_ = &s2[(int)kf_ * TPB + t];                            \
        float2 v_ = *sp_;                                                 \
        v_.x += w_;                                                       \
        v_.y = fmaf(w_, p_, v_.y);                                        \
        *sp_ = v_;                                                        \
    } while (0)

    if (t < ACTIVE && u0 < u1) {
        const float* pp = probas + u0 * ACTIVE + t;
        const long long nu = u1 - u0;
        long long i = 0;
        for (; i + 8 <= nu; i += 8) {
            float p[8];
            #pragma unroll
            for (int j = 0; j < 8; ++j) p[j] = pp[j * ACTIVE];
            #pragma unroll
            for (int j = 0; j < 8; ++j) BODY(p[j]);
            pp += 8 * ACTIVE;
        }
        for (; i < nu; ++i) { BODY(pp[0]); pp += ACTIVE; }
    }
    // element tail (rem multiple of 100 => column map stays consistent)
    if (blockIdx.x == 0 && t < rem) BODY(probas[units * ACTIVE + t]);
    #undef BODY
    __syncthreads();

    // ---- epilogue: fold 5 sub-slots per (col,bin); coalesced stores.
    float* gp = g_part[blockIdx.x];
    for (int idx = t; idx < NSEG; idx += TPB) {       // idx = col*NBINS+b
        const int b   = idx % NBINS;
        const int col = idx / NBINS;
        float cx = 0.0f, sy = 0.0f;
        #pragma unroll
        for (int j = 0; j < 5; ++j) {
            float2 v = s2[b * TPB + col + j * CCOUNT];
            cx += v.x; sy += v.y;
        }
        gp[idx]            = cx;
        gp[NSEG + idx]     = sy;
        gp[2 * NSEG + idx] = s_acc[idx];
    }
}

// -------- finalize: one WARP per output segment, shuffle reduction ---------
__global__ void __launch_bounds__(FBLK) finalize_kernel(float* __restrict__ out) {
    const int k    = blockIdx.x * (FBLK / 32) + (threadIdx.x >> 5);
    const int lane = threadIdx.x & 31;
    if (k >= NSEG) return;

    float cnt = 0.0f, sum = 0.0f, acc = 0.0f;
    for (int b = lane; b < GRID_ACC; b += 32) {
        const float* gp = g_part[b];
        cnt += gp[k];
        sum += gp[NSEG + k];
        acc += gp[2 * NSEG + k];
    }
    #pragma unroll
    for (int o = 16; o > 0; o >>= 1) {
        cnt += __shfl_down_sync(0xffffffffu, cnt, o);
        sum += __shfl_down_sync(0xffffffffu, sum, o);
        acc += __shfl_down_sync(0xffffffffu, acc, o);
    }
    if (lane == 0) {
        float conf, a;
        if (cnt > 0.0f) {
            conf = sum / cnt;
            a    = acc / cnt;
        } else {
            conf = __int_as_float(0x7fc00000);
            a    = conf;
        }
        out[k]            = conf;
        out[NSEG + k]     = a;
        out[2 * NSEG + k] = cnt;
    }
}

extern "C" void kernel_launch(void* const* d_in, const int* in_sizes, int n_in,
                              void* d_out, int out_size) {
    const float* probas = (const float*)d_in[0];
    const void*  labels = d_in[1];
    const int N = in_sizes[0] / CCOUNT;

    const size_t smem = (size_t)SROWS * TPB * sizeof(float2);  // 65536 B
    cudaFuncSetAttribute(accum_kernel,
                         cudaFuncAttributeMaxDynamicSharedMemorySize, (int)smem);

    accum_kernel<<<GRID_ACC, TPB, smem>>>(probas, labels, N);
    const int warps_per_blk = FBLK / 32;
    finalize_kernel<<<(NSEG + warps_per_blk - 1) / warps_per_blk, FBLK>>>(
        (float*)d_out);
}